// round 1
// baseline (speedup 1.0000x reference)
#include <cuda_runtime.h>
#include <math.h>

#define N_NODES 50000
#define N_EDGES 600000
#define DF      128
#define NC      47
#define LDC2    48     // padded row stride for the 47-wide layer
#define BM      64
#define BN      64

// ---------------- scratch (static device globals; no allocation) ------------
__device__ int   g_is64;
__device__ int   g_cnt[N_NODES];
__device__ int   g_rowptr[N_NODES + 1];
__device__ int   g_fill[N_NODES];
__device__ int   g_col[N_EDGES];
__device__ float g_deginv[N_NODES];
__device__ int   g_bsum[64];
__device__ float g_P [N_NODES * DF];
__device__ float g_R [N_NODES * DF];
__device__ float g_H1[N_NODES * DF];
__device__ float g_H2[N_NODES * DF];

// ---------------- edge-index dtype detection (int32 vs int64) ---------------
__global__ void k_detect(const int* __restrict__ w) {
    int bad = 0;
    for (int i = threadIdx.x; i < 4096; i += 32)
        bad |= (w[2 * i + 1] != 0);
    unsigned m = __ballot_sync(0xffffffffu, bad);
    if (threadIdx.x == 0) g_is64 = (m == 0) ? 1 : 0;
}

__device__ __forceinline__ int edge_src(const int* w, int e) {
    return g_is64 ? w[2 * e] : w[e];
}
__device__ __forceinline__ int edge_dst(const int* w, int e) {
    return g_is64 ? w[2 * (N_EDGES + e)] : w[N_EDGES + e];
}

// ---------------- CSR build --------------------------------------------------
__global__ void k_zero_cnt() {
    int i = blockIdx.x * blockDim.x + threadIdx.x;
    if (i < N_NODES) g_cnt[i] = 0;
}

__global__ void k_hist(const int* __restrict__ w) {
    int e = blockIdx.x * blockDim.x + threadIdx.x;
    if (e < N_EDGES) atomicAdd(&g_cnt[edge_dst(w, e)], 1);
}

__global__ void k_scan_blocks() {  // 1024 threads/block
    __shared__ int s[1024];
    int i = blockIdx.x * 1024 + threadIdx.x;
    int v = (i < N_NODES) ? g_cnt[i] : 0;
    s[threadIdx.x] = v;
    __syncthreads();
    for (int off = 1; off < 1024; off <<= 1) {
        int add = (threadIdx.x >= off) ? s[threadIdx.x - off] : 0;
        __syncthreads();
        s[threadIdx.x] += add;
        __syncthreads();
    }
    if (i < N_NODES) g_rowptr[i] = s[threadIdx.x] - v;   // exclusive
    if (threadIdx.x == 1023) g_bsum[blockIdx.x] = s[1023];
}

__global__ void k_scan_sums(int nblocks) {
    if (blockIdx.x == 0 && threadIdx.x == 0) {
        int run = 0;
        for (int b = 0; b < nblocks; b++) {
            int t = g_bsum[b];
            g_bsum[b] = run;
            run += t;
        }
    }
}

__global__ void k_finalize() {
    int i = blockIdx.x * blockDim.x + threadIdx.x;
    if (i < N_NODES) {
        int r = g_rowptr[i] + g_bsum[i >> 10];
        g_rowptr[i] = r;
        g_fill[i]   = r;
        int deg = g_cnt[i];
        g_deginv[i] = 1.0f / (float)(deg > 1 ? deg : 1);
    }
    if (i == 0) g_rowptr[N_NODES] = N_EDGES;
}

__global__ void k_fillcsr(const int* __restrict__ w) {
    int e = blockIdx.x * blockDim.x + threadIdx.x;
    if (e < N_EDGES) {
        int d = edge_dst(w, e);
        int s = edge_src(w, e);
        int pos = atomicAdd(&g_fill[d], 1);
        g_col[pos] = s;
    }
}

// ---------------- GEMM: C[M x F] = A[M x 128] @ W[128 x F] ------------------
// 64x64 tile, full K=128 in shared, 4x4 register tile, 256 threads.
__global__ void k_gemm(const float* __restrict__ A, const float* __restrict__ W,
                       float* __restrict__ C, int M, int F, int ldc)
{
    extern __shared__ float sm[];
    float (*As)[DF + 1] = (float (*)[DF + 1])sm;                 // [64][129]
    float (*Ws)[BN]     = (float (*)[BN])(sm + BM * (DF + 1));   // [128][64]

    int bm = blockIdx.x * BM, bn = blockIdx.y * BN;
    int t = threadIdx.x;

    #pragma unroll
    for (int i = 0; i < 8; i++) {            // 64*128 floats as float4
        int lin = t + i * 256;
        int m  = lin >> 5;
        int k4 = (lin & 31) << 2;
        float4 v = make_float4(0.f, 0.f, 0.f, 0.f);
        int gm = bm + m;
        if (gm < M) v = *(const float4*)(A + (size_t)gm * DF + k4);
        As[m][k4 + 0] = v.x; As[m][k4 + 1] = v.y;
        As[m][k4 + 2] = v.z; As[m][k4 + 3] = v.w;
    }
    #pragma unroll
    for (int i = 0; i < 32; i++) {           // 128*64 scalar (F may be 47)
        int lin = t + i * 256;
        int k = lin >> 6;
        int n = lin & 63;
        int gn = bn + n;
        Ws[k][n] = (gn < F) ? W[(size_t)k * F + gn] : 0.f;
    }
    __syncthreads();

    int tx = t & 15, ty = t >> 4;
    float acc[4][4];
    #pragma unroll
    for (int i = 0; i < 4; i++)
        #pragma unroll
        for (int j = 0; j < 4; j++) acc[i][j] = 0.f;

    #pragma unroll 8
    for (int k = 0; k < DF; k++) {
        float a0 = As[(ty << 2) + 0][k];
        float a1 = As[(ty << 2) + 1][k];
        float a2 = As[(ty << 2) + 2][k];
        float a3 = As[(ty << 2) + 3][k];
        float4 b = *(const float4*)(&Ws[k][tx << 2]);
        acc[0][0] += a0 * b.x; acc[0][1] += a0 * b.y; acc[0][2] += a0 * b.z; acc[0][3] += a0 * b.w;
        acc[1][0] += a1 * b.x; acc[1][1] += a1 * b.y; acc[1][2] += a1 * b.z; acc[1][3] += a1 * b.w;
        acc[2][0] += a2 * b.x; acc[2][1] += a2 * b.y; acc[2][2] += a2 * b.z; acc[2][3] += a2 * b.w;
        acc[3][0] += a3 * b.x; acc[3][1] += a3 * b.y; acc[3][2] += a3 * b.z; acc[3][3] += a3 * b.w;
    }

    #pragma unroll
    for (int i = 0; i < 4; i++) {
        int gm = bm + (ty << 2) + i;
        if (gm >= M) continue;
        #pragma unroll
        for (int j = 0; j < 4; j++) {
            int gn = bn + (tx << 2) + j;
            if (gn < ldc)
                C[(size_t)gm * ldc + gn] = (gn < F) ? acc[i][j] : 0.f;
        }
    }
}

// -------- aggregation: OUT[n] = relu?( mean_nbr(P) + bias + R[n] ) ----------
// warp per node, CSR gather, float4 lanes. P rows are L2-resident (25.6MB).
__global__ void k_aggr(const float* __restrict__ P, const float* __restrict__ R,
                       const float* __restrict__ bias, float* __restrict__ OUT,
                       int F, int ldp, int relu)
{
    int gw   = (blockIdx.x * blockDim.x + threadIdx.x) >> 5;
    int lane = threadIdx.x & 31;
    if (gw >= N_NODES) return;
    int v4 = ldp >> 2;
    int start = g_rowptr[gw], end = g_rowptr[gw + 1];
    if (lane >= v4) return;

    int c0 = lane << 2;
    float4 acc = make_float4(0.f, 0.f, 0.f, 0.f);
    const float* base = P + c0;
    for (int e = start; e < end; e++) {
        int c = g_col[e];
        float4 p = *(const float4*)(base + (size_t)c * ldp);
        acc.x += p.x; acc.y += p.y; acc.z += p.z; acc.w += p.w;
    }
    float inv = g_deginv[gw];
    float4 r = *(const float4*)(R + (size_t)gw * ldp + c0);
    float av[4] = {acc.x, acc.y, acc.z, acc.w};
    float rv[4] = {r.x, r.y, r.z, r.w};
    float4 ov;
    float* po = (float*)&ov;
    #pragma unroll
    for (int j = 0; j < 4; j++) {
        int cc = c0 + j;
        float val = 0.f;
        if (cc < F) {
            val = av[j] * inv + bias[cc] + rv[j];
            if (relu) val = fmaxf(val, 0.f);
        }
        po[j] = val;
    }
    *(float4*)(OUT + (size_t)gw * ldp + c0) = ov;
}

// -------- epilogue: L2 normalize (eps 1e-12) + log_softmax, warp/node -------
__global__ void k_out(const float* __restrict__ L, float* __restrict__ out)
{
    int gw   = (blockIdx.x * blockDim.x + threadIdx.x) >> 5;
    int lane = threadIdx.x & 31;
    if (gw >= N_NODES) return;
    const float* row = L + (size_t)gw * LDC2;
    bool v0 = (lane < NC);
    bool v1 = (lane + 32 < NC);
    float x0 = v0 ? row[lane]      : 0.f;
    float x1 = v1 ? row[lane + 32] : 0.f;

    float ss = x0 * x0 + x1 * x1;
    #pragma unroll
    for (int o = 16; o; o >>= 1) ss += __shfl_xor_sync(0xffffffffu, ss, o);
    float inv = 1.0f / fmaxf(sqrtf(ss), 1e-12f);
    x0 *= inv; x1 *= inv;

    float m = fmaxf(v0 ? x0 : -1e30f, v1 ? x1 : -1e30f);
    #pragma unroll
    for (int o = 16; o; o >>= 1) m = fmaxf(m, __shfl_xor_sync(0xffffffffu, m, o));

    float s = (v0 ? expf(x0 - m) : 0.f) + (v1 ? expf(x1 - m) : 0.f);
    #pragma unroll
    for (int o = 16; o; o >>= 1) s += __shfl_xor_sync(0xffffffffu, s, o);
    float ls = m + logf(s);

    if (v0) out[(size_t)gw * NC + lane]      = x0 - ls;
    if (v1) out[(size_t)gw * NC + lane + 32] = x1 - ls;
}

// ---------------- host ------------------------------------------------------
extern "C" void kernel_launch(void* const* d_in, const int* in_sizes, int n_in,
                              void* d_out, int out_size)
{
    const float* x   = (const float*)d_in[0];
    const int*   ei  = (const int*)  d_in[1];   // int32 or int64; detected on-device
    const float* Wl0 = (const float*)d_in[2];
    const float* bl0 = (const float*)d_in[3];
    const float* Wr0 = (const float*)d_in[4];
    const float* Wl1 = (const float*)d_in[5];
    const float* bl1 = (const float*)d_in[6];
    const float* Wr1 = (const float*)d_in[7];
    const float* Wl2 = (const float*)d_in[8];
    const float* bl2 = (const float*)d_in[9];
    const float* Wr2 = (const float*)d_in[10];
    float* out = (float*)d_out;

    float *P, *R, *H1, *H2;
    cudaGetSymbolAddress((void**)&P,  g_P);
    cudaGetSymbolAddress((void**)&R,  g_R);
    cudaGetSymbolAddress((void**)&H1, g_H1);
    cudaGetSymbolAddress((void**)&H2, g_H2);

    const int SMEM_GEMM = (BM * (DF + 1) + DF * BN) * (int)sizeof(float); // 65792
    cudaFuncSetAttribute(k_gemm, cudaFuncAttributeMaxDynamicSharedMemorySize, SMEM_GEMM);

    // ---- CSR build (per launch; deterministic up to float-sum order) ----
    k_detect<<<1, 32>>>(ei);
    k_zero_cnt<<<(N_NODES + 255) / 256, 256>>>();
    k_hist<<<(N_EDGES + 255) / 256, 256>>>(ei);
    int nsb = (N_NODES + 1023) / 1024;
    k_scan_blocks<<<nsb, 1024>>>();
    k_scan_sums<<<1, 32>>>(nsb);
    k_finalize<<<(N_NODES + 255) / 256, 256>>>();
    k_fillcsr<<<(N_EDGES + 255) / 256, 256>>>(ei);

    dim3 g128((N_NODES + BM - 1) / BM, (DF + BN - 1) / BN);   // (782, 2)
    dim3 g47 ((N_NODES + BM - 1) / BM, 1);
    int agb = (N_NODES * 32 + 255) / 256;

    // layer 0: project-first (mean is linear), aggregate projected rows
    k_gemm<<<g128, 256, SMEM_GEMM>>>(x, Wl0, P, N_NODES, DF, DF);
    k_gemm<<<g128, 256, SMEM_GEMM>>>(x, Wr0, R, N_NODES, DF, DF);
    k_aggr<<<agb, 256>>>(P, R, bl0, H1, DF, DF, 1);

    // layer 1
    k_gemm<<<g128, 256, SMEM_GEMM>>>(H1, Wl1, P, N_NODES, DF, DF);
    k_gemm<<<g128, 256, SMEM_GEMM>>>(H1, Wr1, R, N_NODES, DF, DF);
    k_aggr<<<agb, 256>>>(P, R, bl1, H2, DF, DF, 1);

    // layer 2 (47-wide, padded to 48) — aggregation traffic cut 128->48
    k_gemm<<<g47, 256, SMEM_GEMM>>>(H2, Wl2, P, N_NODES, NC, LDC2);
    k_gemm<<<g47, 256, SMEM_GEMM>>>(H2, Wr2, R, N_NODES, NC, LDC2);
    k_aggr<<<agb, 256>>>(P, R, bl2, H1, NC, LDC2, 0);

    // normalize + log_softmax
    k_out<<<agb, 256>>>(H1, out);
}

// round 2
// speedup vs baseline: 1.6275x; 1.6275x over previous
#include <cuda_runtime.h>
#include <math.h>
#include <stdint.h>

#define N_NODES 50000
#define N_EDGES 600000
#define DF      128
#define NC      47
#define LDC2    48     // padded row stride for the 47-wide layer

// ---------------- scratch (static device globals; no allocation) ------------
__device__ int   g_is64;
__device__ int   g_cnt[N_NODES];
__device__ int   g_rowptr[N_NODES + 1];
__device__ int   g_fill[N_NODES];
__device__ int   g_col[N_EDGES];
__device__ float g_deginv[N_NODES];
__device__ int   g_bsum[64];
__device__ float g_P [N_NODES * DF];
__device__ float g_R [N_NODES * DF];
__device__ float g_H1[N_NODES * DF];
__device__ float g_H2[N_NODES * DF];

// ---------------- edge-index dtype detection (int32 vs int64) ---------------
__global__ void k_detect(const int* __restrict__ w) {
    int bad = 0;
    for (int i = threadIdx.x; i < 4096; i += 32)
        bad |= (w[2 * i + 1] != 0);
    unsigned m = __ballot_sync(0xffffffffu, bad);
    if (threadIdx.x == 0) g_is64 = (m == 0) ? 1 : 0;
}

__device__ __forceinline__ int edge_src(const int* w, int e) {
    return g_is64 ? w[2 * e] : w[e];
}
__device__ __forceinline__ int edge_dst(const int* w, int e) {
    return g_is64 ? w[2 * (N_EDGES + e)] : w[N_EDGES + e];
}

// ---------------- CSR build --------------------------------------------------
__global__ void k_zero_cnt() {
    int i = blockIdx.x * blockDim.x + threadIdx.x;
    if (i < N_NODES) g_cnt[i] = 0;
}

__global__ void k_hist(const int* __restrict__ w) {
    int e = blockIdx.x * blockDim.x + threadIdx.x;
    if (e < N_EDGES) atomicAdd(&g_cnt[edge_dst(w, e)], 1);
}

__global__ void k_scan_blocks() {  // 1024 threads/block
    __shared__ int s[1024];
    int i = blockIdx.x * 1024 + threadIdx.x;
    int v = (i < N_NODES) ? g_cnt[i] : 0;
    s[threadIdx.x] = v;
    __syncthreads();
    for (int off = 1; off < 1024; off <<= 1) {
        int add = (threadIdx.x >= off) ? s[threadIdx.x - off] : 0;
        __syncthreads();
        s[threadIdx.x] += add;
        __syncthreads();
    }
    if (i < N_NODES) g_rowptr[i] = s[threadIdx.x] - v;   // exclusive
    if (threadIdx.x == 1023) g_bsum[blockIdx.x] = s[1023];
}

__global__ void k_scan_sums(int nblocks) {
    if (blockIdx.x == 0 && threadIdx.x == 0) {
        int run = 0;
        for (int b = 0; b < nblocks; b++) {
            int t = g_bsum[b];
            g_bsum[b] = run;
            run += t;
        }
    }
}

__global__ void k_finalize() {
    int i = blockIdx.x * blockDim.x + threadIdx.x;
    if (i < N_NODES) {
        int r = g_rowptr[i] + g_bsum[i >> 10];
        g_rowptr[i] = r;
        g_fill[i]   = r;
        int deg = g_cnt[i];
        g_deginv[i] = 1.0f / (float)(deg > 1 ? deg : 1);
    }
    if (i == 0) g_rowptr[N_NODES] = N_EDGES;
}

__global__ void k_fillcsr(const int* __restrict__ w) {
    int e = blockIdx.x * blockDim.x + threadIdx.x;
    if (e < N_EDGES) {
        int d = edge_dst(w, e);
        int s = edge_src(w, e);
        int pos = atomicAdd(&g_fill[d], 1);
        g_col[pos] = s;
    }
}

// ---------------- tf32 tensor-core GEMM -------------------------------------
// C[M x F] = A[M x 128] @ W[128 x F], padded out to ldc with zeros.
// Block = 128 rows x BN cols (BN = NJ*16). Full K=128 resident in smem.
// 8 warps: 4 m-groups x 2 n-groups; warp tile = 32 x NJ*8.
// Smem strides chosen so all fragment loads are bank-conflict-free.

__device__ __forceinline__ uint32_t f2tf32(float x) {
    uint32_t r;
    asm("cvt.rna.tf32.f32 %0, %1;" : "=r"(r) : "f"(x));
    return r;
}

__device__ __forceinline__ void mma_tf32(float* d, const uint32_t* a, const uint32_t* b) {
    asm volatile(
        "mma.sync.aligned.m16n8k8.row.col.f32.tf32.tf32.f32 "
        "{%0,%1,%2,%3},{%4,%5,%6,%7},{%8,%9},{%0,%1,%2,%3};"
        : "+f"(d[0]), "+f"(d[1]), "+f"(d[2]), "+f"(d[3])
        : "r"(a[0]), "r"(a[1]), "r"(a[2]), "r"(a[3]), "r"(b[0]), "r"(b[1]));
}

template<int NJ>   // n-tiles (8 wide) per warp; BN = NJ*16
__global__ void __launch_bounds__(256, 1)
k_gemm_tc(const float* __restrict__ A, const float* __restrict__ W,
          float* __restrict__ C, int M, int F, int ldc)
{
    constexpr int BN      = NJ * 16;
    constexpr int ASTRIDE = 132;                 // 132 % 32 == 4 -> conflict-free A frags
    constexpr int BSTRIDE = (NJ == 8) ? 136 : 56; // % 32 == 8 -> conflict-free B frags
    extern __shared__ float smf[];
    float* As = smf;                        // [128][ASTRIDE]
    float* Bs = smf + 128 * ASTRIDE;        // [128][BSTRIDE]

    int bm = blockIdx.x * 128;
    int t  = threadIdx.x;

    // load A tile (128 x 128), convert to tf32 bits
    #pragma unroll
    for (int i = 0; i < 16; i++) {
        int lin = t + i * 256;               // 4096 float4 slots
        int m  = lin >> 5;
        int k4 = (lin & 31) << 2;
        float4 v = make_float4(0.f, 0.f, 0.f, 0.f);
        if (bm + m < M) v = *(const float4*)(A + (size_t)(bm + m) * DF + k4);
        As[m * ASTRIDE + k4 + 0] = __uint_as_float(f2tf32(v.x));
        As[m * ASTRIDE + k4 + 1] = __uint_as_float(f2tf32(v.y));
        As[m * ASTRIDE + k4 + 2] = __uint_as_float(f2tf32(v.z));
        As[m * ASTRIDE + k4 + 3] = __uint_as_float(f2tf32(v.w));
    }
    // load W (128 x BN), zero-padded past F
    #pragma unroll
    for (int i = 0; i < BN / 2; i++) {
        int lin = t + i * 256;
        int k = lin / BN;
        int n = lin % BN;
        float v = (n < F) ? W[(size_t)k * F + n] : 0.f;
        Bs[k * BSTRIDE + n] = __uint_as_float(f2tf32(v));
    }
    __syncthreads();

    int warp = t >> 5, lane = t & 31;
    int wm = (warp & 3) * 32;
    int wn = (warp >> 2) * (NJ * 8);
    int group = lane >> 2, tig = lane & 3;

    float acc[2][NJ][4];
    #pragma unroll
    for (int i = 0; i < 2; i++)
        #pragma unroll
        for (int j = 0; j < NJ; j++)
            #pragma unroll
            for (int q = 0; q < 4; q++) acc[i][j][q] = 0.f;

    #pragma unroll 2
    for (int k0 = 0; k0 < DF; k0 += 8) {
        uint32_t a[2][4], b[NJ][2];
        #pragma unroll
        for (int i = 0; i < 2; i++) {
            const float* p = As + (wm + i * 16 + group) * ASTRIDE + k0 + tig;
            a[i][0] = *(const uint32_t*)p;
            a[i][1] = *(const uint32_t*)(p + 8 * ASTRIDE);
            a[i][2] = *(const uint32_t*)(p + 4);
            a[i][3] = *(const uint32_t*)(p + 8 * ASTRIDE + 4);
        }
        #pragma unroll
        for (int j = 0; j < NJ; j++) {
            const float* p = Bs + (size_t)(k0 + tig) * BSTRIDE + wn + j * 8 + group;
            b[j][0] = *(const uint32_t*)p;
            b[j][1] = *(const uint32_t*)(p + 4 * BSTRIDE);
        }
        #pragma unroll
        for (int i = 0; i < 2; i++)
            #pragma unroll
            for (int j = 0; j < NJ; j++)
                mma_tf32(acc[i][j], a[i], b[j]);
    }

    // epilogue: scatter fragments, zero-pad cols F..ldc-1
    #pragma unroll
    for (int i = 0; i < 2; i++) {
        int gm0 = bm + wm + i * 16 + group;
        #pragma unroll
        for (int j = 0; j < NJ; j++) {
            int gn = wn + j * 8 + 2 * tig;       // < BN == ldc
            if (gm0 < M) {
                C[(size_t)gm0 * ldc + gn]     = (gn     < F) ? acc[i][j][0] : 0.f;
                C[(size_t)gm0 * ldc + gn + 1] = (gn + 1 < F) ? acc[i][j][1] : 0.f;
            }
            if (gm0 + 8 < M) {
                C[(size_t)(gm0 + 8) * ldc + gn]     = (gn     < F) ? acc[i][j][2] : 0.f;
                C[(size_t)(gm0 + 8) * ldc + gn + 1] = (gn + 1 < F) ? acc[i][j][3] : 0.f;
            }
        }
    }
}

// -------- aggregation: OUT[n] = relu?( mean_nbr(P) + bias + R[n] ) ----------
__global__ void k_aggr(const float* __restrict__ P, const float* __restrict__ R,
                       const float* __restrict__ bias, float* __restrict__ OUT,
                       int F, int ldp, int relu)
{
    int gw   = (blockIdx.x * blockDim.x + threadIdx.x) >> 5;
    int lane = threadIdx.x & 31;
    if (gw >= N_NODES) return;
    int v4 = ldp >> 2;
    int start = g_rowptr[gw], end = g_rowptr[gw + 1];
    if (lane >= v4) return;

    int c0 = lane << 2;
    float4 acc = make_float4(0.f, 0.f, 0.f, 0.f);
    const float* base = P + c0;
    for (int e = start; e < end; e++) {
        int c = g_col[e];
        float4 p = *(const float4*)(base + (size_t)c * ldp);
        acc.x += p.x; acc.y += p.y; acc.z += p.z; acc.w += p.w;
    }
    float inv = g_deginv[gw];
    float4 r = *(const float4*)(R + (size_t)gw * ldp + c0);
    float av[4] = {acc.x, acc.y, acc.z, acc.w};
    float rv[4] = {r.x, r.y, r.z, r.w};
    float4 ov;
    float* po = (float*)&ov;
    #pragma unroll
    for (int j = 0; j < 4; j++) {
        int cc = c0 + j;
        float val = 0.f;
        if (cc < F) {
            val = av[j] * inv + bias[cc] + rv[j];
            if (relu) val = fmaxf(val, 0.f);
        }
        po[j] = val;
    }
    *(float4*)(OUT + (size_t)gw * ldp + c0) = ov;
}

// -------- epilogue: L2 normalize (eps 1e-12) + log_softmax, warp/node -------
__global__ void k_out(const float* __restrict__ L, float* __restrict__ out)
{
    int gw   = (blockIdx.x * blockDim.x + threadIdx.x) >> 5;
    int lane = threadIdx.x & 31;
    if (gw >= N_NODES) return;
    const float* row = L + (size_t)gw * LDC2;
    bool v0 = (lane < NC);
    bool v1 = (lane + 32 < NC);
    float x0 = v0 ? row[lane]      : 0.f;
    float x1 = v1 ? row[lane + 32] : 0.f;

    float ss = x0 * x0 + x1 * x1;
    #pragma unroll
    for (int o = 16; o; o >>= 1) ss += __shfl_xor_sync(0xffffffffu, ss, o);
    float inv = 1.0f / fmaxf(sqrtf(ss), 1e-12f);
    x0 *= inv; x1 *= inv;

    float m = fmaxf(v0 ? x0 : -1e30f, v1 ? x1 : -1e30f);
    #pragma unroll
    for (int o = 16; o; o >>= 1) m = fmaxf(m, __shfl_xor_sync(0xffffffffu, m, o));

    float s = (v0 ? expf(x0 - m) : 0.f) + (v1 ? expf(x1 - m) : 0.f);
    #pragma unroll
    for (int o = 16; o; o >>= 1) s += __shfl_xor_sync(0xffffffffu, s, o);
    float ls = m + logf(s);

    if (v0) out[(size_t)gw * NC + lane]      = x0 - ls;
    if (v1) out[(size_t)gw * NC + lane + 32] = x1 - ls;
}

// ---------------- host ------------------------------------------------------
extern "C" void kernel_launch(void* const* d_in, const int* in_sizes, int n_in,
                              void* d_out, int out_size)
{
    const float* x   = (const float*)d_in[0];
    const int*   ei  = (const int*)  d_in[1];   // int32 or int64; detected on-device
    const float* Wl0 = (const float*)d_in[2];
    const float* bl0 = (const float*)d_in[3];
    const float* Wr0 = (const float*)d_in[4];
    const float* Wl1 = (const float*)d_in[5];
    const float* bl1 = (const float*)d_in[6];
    const float* Wr1 = (const float*)d_in[7];
    const float* Wl2 = (const float*)d_in[8];
    const float* bl2 = (const float*)d_in[9];
    const float* Wr2 = (const float*)d_in[10];
    float* out = (float*)d_out;

    float *P, *R, *H1, *H2;
    cudaGetSymbolAddress((void**)&P,  g_P);
    cudaGetSymbolAddress((void**)&R,  g_R);
    cudaGetSymbolAddress((void**)&H1, g_H1);
    cudaGetSymbolAddress((void**)&H2, g_H2);

    const int SMEM_G8 = (128 * 132 + 128 * 136) * (int)sizeof(float); // 137216
    const int SMEM_G3 = (128 * 132 + 128 * 56)  * (int)sizeof(float); //  96256
    cudaFuncSetAttribute(k_gemm_tc<8>, cudaFuncAttributeMaxDynamicSharedMemorySize, SMEM_G8);
    cudaFuncSetAttribute(k_gemm_tc<3>, cudaFuncAttributeMaxDynamicSharedMemorySize, SMEM_G3);

    // ---- CSR build ----
    k_detect<<<1, 32>>>(ei);
    k_zero_cnt<<<(N_NODES + 255) / 256, 256>>>();
    k_hist<<<(N_EDGES + 255) / 256, 256>>>(ei);
    int nsb = (N_NODES + 1023) / 1024;
    k_scan_blocks<<<nsb, 1024>>>();
    k_scan_sums<<<1, 32>>>(nsb);
    k_finalize<<<(N_NODES + 255) / 256, 256>>>();
    k_fillcsr<<<(N_EDGES + 255) / 256, 256>>>(ei);

    int gmb = (N_NODES + 127) / 128;   // 391
    int agb = (N_NODES * 32 + 255) / 256;

    // layer 0: project-first (mean is linear), aggregate projected rows
    k_gemm_tc<8><<<gmb, 256, SMEM_G8>>>(x, Wl0, P, N_NODES, DF, DF);
    k_gemm_tc<8><<<gmb, 256, SMEM_G8>>>(x, Wr0, R, N_NODES, DF, DF);
    k_aggr<<<agb, 256>>>(P, R, bl0, H1, DF, DF, 1);

    // layer 1
    k_gemm_tc<8><<<gmb, 256, SMEM_G8>>>(H1, Wl1, P, N_NODES, DF, DF);
    k_gemm_tc<8><<<gmb, 256, SMEM_G8>>>(H1, Wr1, R, N_NODES, DF, DF);
    k_aggr<<<agb, 256>>>(P, R, bl1, H2, DF, DF, 1);

    // layer 2 (47-wide, padded to 48)
    k_gemm_tc<3><<<gmb, 256, SMEM_G3>>>(H2, Wl2, P, N_NODES, NC, LDC2);
    k_gemm_tc<3><<<gmb, 256, SMEM_G3>>>(H2, Wr2, R, N_NODES, NC, LDC2);
    k_aggr<<<agb, 256>>>(P, R, bl2, H1, NC, LDC2, 0);

    // normalize + log_softmax
    k_out<<<agb, 256>>>(H1, out);
}

// round 3
// speedup vs baseline: 1.9165x; 1.1775x over previous
#include <cuda_runtime.h>
#include <math.h>
#include <stdint.h>

#define N_NODES 50000
#define N_EDGES 600000
#define DF      128
#define NC      47
#define LDC2    48

// ---------------- scratch ----------------------------------------------------
__device__ int   g_is64;
__device__ int   g_cnt[N_NODES];
__device__ int   g_rowptr[N_NODES + 1];
__device__ int   g_fill[N_NODES];
__device__ int   g_col[N_EDGES];
__device__ float g_deginv[N_NODES];
__device__ int   g_bsum[64];
__device__ float g_P [N_NODES * DF];
__device__ float g_R [N_NODES * DF];
__device__ float g_H1[N_NODES * DF];
__device__ float g_H2[N_NODES * DF];

// ---------------- CSR build ---------------------------------------------------
__global__ void k_zero_detect(const int* __restrict__ w) {
    int i = blockIdx.x * blockDim.x + threadIdx.x;
    if (i < N_NODES) g_cnt[i] = 0;
    if (blockIdx.x == 0 && threadIdx.x < 32) {
        int bad = 0;
        for (int j = threadIdx.x; j < 4096; j += 32)
            bad |= (w[2 * j + 1] != 0);
        unsigned m = __ballot_sync(0xffffffffu, bad);
        if (threadIdx.x == 0) g_is64 = (m == 0) ? 1 : 0;
    }
}

__device__ __forceinline__ int edge_src(const int* w, int e) {
    return g_is64 ? w[2 * e] : w[e];
}
__device__ __forceinline__ int edge_dst(const int* w, int e) {
    return g_is64 ? w[2 * (N_EDGES + e)] : w[N_EDGES + e];
}

__global__ void k_hist(const int* __restrict__ w) {
    int e = blockIdx.x * blockDim.x + threadIdx.x;
    if (e < N_EDGES) atomicAdd(&g_cnt[edge_dst(w, e)], 1);
}

// 1024-thread block scan: warp shuffle scan + warp-sum scan
__global__ void k_scan_blocks() {
    __shared__ int wsum[32];
    int i = blockIdx.x * 1024 + threadIdx.x;
    int lane = threadIdx.x & 31, warp = threadIdx.x >> 5;
    int v = (i < N_NODES) ? g_cnt[i] : 0;
    int s = v;
    #pragma unroll
    for (int off = 1; off < 32; off <<= 1) {
        int t = __shfl_up_sync(0xffffffffu, s, off);
        if (lane >= off) s += t;
    }
    if (lane == 31) wsum[warp] = s;
    __syncthreads();
    if (warp == 0) {
        int ws = wsum[lane];
        #pragma unroll
        for (int off = 1; off < 32; off <<= 1) {
            int t = __shfl_up_sync(0xffffffffu, ws, off);
            if (lane >= off) ws += t;
        }
        wsum[lane] = ws;
    }
    __syncthreads();
    int incl = s + (warp ? wsum[warp - 1] : 0);
    if (i < N_NODES) g_rowptr[i] = incl - v;       // exclusive
    if (threadIdx.x == 1023) g_bsum[blockIdx.x] = incl;
}

__global__ void k_scan_sums(int nblocks) {
    if (threadIdx.x == 0) {
        int run = 0;
        for (int b = 0; b < nblocks; b++) {
            int t = g_bsum[b];
            g_bsum[b] = run;
            run += t;
        }
    }
}

__global__ void k_finalize() {
    int i = blockIdx.x * blockDim.x + threadIdx.x;
    if (i < N_NODES) {
        int r = g_rowptr[i] + g_bsum[i >> 10];
        g_rowptr[i] = r;
        g_fill[i]   = r;
        int deg = g_cnt[i];
        g_deginv[i] = 1.0f / (float)(deg > 1 ? deg : 1);
    }
    if (i == 0) g_rowptr[N_NODES] = N_EDGES;
}

__global__ void k_fillcsr(const int* __restrict__ w) {
    int e = blockIdx.x * blockDim.x + threadIdx.x;
    if (e < N_EDGES) {
        int d = edge_dst(w, e);
        int s = edge_src(w, e);
        int pos = atomicAdd(&g_fill[d], 1);
        g_col[pos] = s;
    }
}

// ---------------- fused dual tf32 tensor-core GEMM ---------------------------
// P = A @ Wl, R = A @ Wr, both [M x NPER] (NPER = row stride, zero-padded
// past F). A loaded to smem ONCE for both. Block = 128 rows, 512 threads,
// 16 warps: 4 m-groups x 4 n-groups over total width 2*NPER.

__device__ __forceinline__ uint32_t f2tf32(float x) {
    uint32_t r;
    asm("cvt.rna.tf32.f32 %0, %1;" : "=r"(r) : "f"(x));
    return r;
}

__device__ __forceinline__ void mma_tf32(float* d, const uint32_t* a, const uint32_t* b) {
    asm volatile(
        "mma.sync.aligned.m16n8k8.row.col.f32.tf32.tf32.f32 "
        "{%0,%1,%2,%3},{%4,%5,%6,%7},{%8,%9},{%0,%1,%2,%3};"
        : "+f"(d[0]), "+f"(d[1]), "+f"(d[2]), "+f"(d[3])
        : "r"(a[0]), "r"(a[1]), "r"(a[2]), "r"(a[3]), "r"(b[0]), "r"(b[1]));
}

template<int NPER>   // 128 (hidden) or 48 (classifier, F=47)
__global__ void __launch_bounds__(512, 1)
k_gemm2(const float* __restrict__ A,
        const float* __restrict__ Wl, const float* __restrict__ Wr,
        float* __restrict__ P, float* __restrict__ R, int M, int F)
{
    constexpr int BN      = 2 * NPER;          // 256 or 96
    constexpr int NW      = BN / 4;            // per-warp n extent: 64 or 24
    constexpr int NJ      = NW / 8;            // 8 or 3
    constexpr int ASTRIDE = 132;               // %32 == 4
    constexpr int BSTRIDE = BN + 8;            // 264 / 104, %32 == 8
    extern __shared__ float smf[];
    float* As = smf;                           // [128][ASTRIDE]
    float* Bs = smf + 128 * ASTRIDE;           // [128][BSTRIDE]

    int bm = blockIdx.x * 128;
    int t  = threadIdx.x;

    // A tile (128 x 128) -> tf32 smem, zero-fill beyond M
    #pragma unroll
    for (int i = 0; i < 8; i++) {
        int lin = t + i * 512;                 // 4096 float4 slots
        int m  = lin >> 5;
        int k4 = (lin & 31) << 2;
        float4 v = make_float4(0.f, 0.f, 0.f, 0.f);
        if (bm + m < M) v = *(const float4*)(A + (size_t)(bm + m) * DF + k4);
        As[m * ASTRIDE + k4 + 0] = __uint_as_float(f2tf32(v.x));
        As[m * ASTRIDE + k4 + 1] = __uint_as_float(f2tf32(v.y));
        As[m * ASTRIDE + k4 + 2] = __uint_as_float(f2tf32(v.z));
        As[m * ASTRIDE + k4 + 3] = __uint_as_float(f2tf32(v.w));
    }
    // B tile: [128 x BN] = concat(Wl, Wr) columns, tf32, zero-padded past F
    if constexpr (NPER == 128) {
        #pragma unroll
        for (int i = 0; i < 16; i++) {         // 8192 float4 slots
            int lin = t + i * 512;
            int n4 = (lin & 63) << 2;
            int k  = lin >> 6;
            const float* src = (n4 < 128) ? (Wl + (size_t)k * 128 + n4)
                                          : (Wr + (size_t)k * 128 + n4 - 128);
            float4 v = *(const float4*)src;
            Bs[k * BSTRIDE + n4 + 0] = __uint_as_float(f2tf32(v.x));
            Bs[k * BSTRIDE + n4 + 1] = __uint_as_float(f2tf32(v.y));
            Bs[k * BSTRIDE + n4 + 2] = __uint_as_float(f2tf32(v.z));
            Bs[k * BSTRIDE + n4 + 3] = __uint_as_float(f2tf32(v.w));
        }
    } else {
        #pragma unroll
        for (int i = 0; i < 24; i++) {         // 128*96 scalars
            int lin = t + i * 512;
            int n = lin % BN;
            int k = lin / BN;
            int c = (n < NPER) ? n : n - NPER;
            const float* W = (n < NPER) ? Wl : Wr;
            float v = (c < F) ? W[(size_t)k * F + c] : 0.f;
            Bs[k * BSTRIDE + n] = __uint_as_float(f2tf32(v));
        }
    }
    __syncthreads();

    int warp = t >> 5, lane = t & 31;
    int wm = (warp & 3) * 32;
    int wn = (warp >> 2) * NW;
    int group = lane >> 2, tig = lane & 3;

    float acc[2][NJ][4];
    #pragma unroll
    for (int i = 0; i < 2; i++)
        #pragma unroll
        for (int j = 0; j < NJ; j++)
            #pragma unroll
            for (int q = 0; q < 4; q++) acc[i][j][q] = 0.f;

    #pragma unroll 4
    for (int k0 = 0; k0 < DF; k0 += 8) {
        uint32_t a[2][4], b[NJ][2];
        #pragma unroll
        for (int i = 0; i < 2; i++) {
            const float* p = As + (wm + i * 16 + group) * ASTRIDE + k0 + tig;
            a[i][0] = *(const uint32_t*)p;
            a[i][1] = *(const uint32_t*)(p + 8 * ASTRIDE);
            a[i][2] = *(const uint32_t*)(p + 4);
            a[i][3] = *(const uint32_t*)(p + 8 * ASTRIDE + 4);
        }
        #pragma unroll
        for (int j = 0; j < NJ; j++) {
            const float* p = Bs + (size_t)(k0 + tig) * BSTRIDE + wn + j * 8 + group;
            b[j][0] = *(const uint32_t*)p;
            b[j][1] = *(const uint32_t*)(p + 4 * BSTRIDE);
        }
        #pragma unroll
        for (int i = 0; i < 2; i++)
            #pragma unroll
            for (int j = 0; j < NJ; j++)
                mma_tf32(acc[i][j], a[i], b[j]);
    }

    // epilogue: n < NPER -> P, else -> R; zero-pad cols >= F
    #pragma unroll
    for (int i = 0; i < 2; i++) {
        int gm0 = bm + wm + i * 16 + group;
        #pragma unroll
        for (int j = 0; j < NJ; j++) {
            int gn = wn + j * 8 + 2 * tig;
            float* dst;
            int col;
            if (gn < NPER) { dst = P; col = gn; }
            else           { dst = R; col = gn - NPER; }
            float v0 = (col     < F) ? acc[i][j][0] : 0.f;
            float v1 = (col + 1 < F) ? acc[i][j][1] : 0.f;
            float v2 = (col     < F) ? acc[i][j][2] : 0.f;
            float v3 = (col + 1 < F) ? acc[i][j][3] : 0.f;
            if (gm0 < M) {
                dst[(size_t)gm0 * NPER + col]     = v0;
                dst[(size_t)gm0 * NPER + col + 1] = v1;
            }
            if (gm0 + 8 < M) {
                dst[(size_t)(gm0 + 8) * NPER + col]     = v2;
                dst[(size_t)(gm0 + 8) * NPER + col + 1] = v3;
            }
        }
    }
}

// -------- aggregation (hidden layers): OUT = relu(mean_nbr(P)+b+R) ----------
__global__ void k_aggr(const float* __restrict__ P, const float* __restrict__ R,
                       const float* __restrict__ bias, float* __restrict__ OUT)
{
    int gw   = (blockIdx.x * blockDim.x + threadIdx.x) >> 5;
    int lane = threadIdx.x & 31;
    if (gw >= N_NODES) return;
    int start = g_rowptr[gw], end = g_rowptr[gw + 1];

    int c0 = lane << 2;
    float4 acc = make_float4(0.f, 0.f, 0.f, 0.f);
    const float* base = P + c0;
    for (int e = start; e < end; e++) {
        int c = g_col[e];
        float4 p = *(const float4*)(base + (size_t)c * DF);
        acc.x += p.x; acc.y += p.y; acc.z += p.z; acc.w += p.w;
    }
    float inv = g_deginv[gw];
    float4 r = *(const float4*)(R + (size_t)gw * DF + c0);
    float4 b = *(const float4*)(bias + c0);
    float4 ov;
    ov.x = fmaxf(acc.x * inv + b.x + r.x, 0.f);
    ov.y = fmaxf(acc.y * inv + b.y + r.y, 0.f);
    ov.z = fmaxf(acc.z * inv + b.z + r.z, 0.f);
    ov.w = fmaxf(acc.w * inv + b.w + r.w, 0.f);
    *(float4*)(OUT + (size_t)gw * DF + c0) = ov;
}

// -------- fused layer-2: aggr + L2-normalize + log_softmax -> out -----------
__global__ void k_aggr_out(const float* __restrict__ P, const float* __restrict__ R,
                           const float* __restrict__ bias, float* __restrict__ out)
{
    int gw   = (blockIdx.x * blockDim.x + threadIdx.x) >> 5;
    int lane = threadIdx.x & 31;
    if (gw >= N_NODES) return;
    bool act = (lane < 12);                    // 12 lanes x 4 = 48 cols
    int c0 = lane << 2;

    float v[4] = {0.f, 0.f, 0.f, 0.f};
    if (act) {
        int start = g_rowptr[gw], end = g_rowptr[gw + 1];
        float4 acc = make_float4(0.f, 0.f, 0.f, 0.f);
        const float* base = P + c0;
        for (int e = start; e < end; e++) {
            int c = g_col[e];
            float4 p = *(const float4*)(base + (size_t)c * LDC2);
            acc.x += p.x; acc.y += p.y; acc.z += p.z; acc.w += p.w;
        }
        float inv = g_deginv[gw];
        float4 r = *(const float4*)(R + (size_t)gw * LDC2 + c0);
        float av[4] = {acc.x, acc.y, acc.z, acc.w};
        float rv[4] = {r.x, r.y, r.z, r.w};
        #pragma unroll
        for (int j = 0; j < 4; j++) {
            int cc = c0 + j;
            if (cc < NC) v[j] = av[j] * inv + bias[cc] + rv[j];
        }
    }

    // L2 norm (cols >= 47 are 0)
    float ss = v[0]*v[0] + v[1]*v[1] + v[2]*v[2] + v[3]*v[3];
    #pragma unroll
    for (int o = 16; o; o >>= 1) ss += __shfl_xor_sync(0xffffffffu, ss, o);
    float inv = 1.0f / fmaxf(sqrtf(ss), 1e-12f);
    #pragma unroll
    for (int j = 0; j < 4; j++) v[j] *= inv;

    // log_softmax over 47 valid cols
    float m = -1e30f;
    #pragma unroll
    for (int j = 0; j < 4; j++)
        if (act && (c0 + j) < NC) m = fmaxf(m, v[j]);
    #pragma unroll
    for (int o = 16; o; o >>= 1) m = fmaxf(m, __shfl_xor_sync(0xffffffffu, m, o));

    float s = 0.f;
    #pragma unroll
    for (int j = 0; j < 4; j++)
        if (act && (c0 + j) < NC) s += expf(v[j] - m);
    #pragma unroll
    for (int o = 16; o; o >>= 1) s += __shfl_xor_sync(0xffffffffu, s, o);
    float ls = m + logf(s);

    if (act) {
        #pragma unroll
        for (int j = 0; j < 4; j++) {
            int cc = c0 + j;
            if (cc < NC) out[(size_t)gw * NC + cc] = v[j] - ls;
        }
    }
}

// ---------------- host --------------------------------------------------------
extern "C" void kernel_launch(void* const* d_in, const int* in_sizes, int n_in,
                              void* d_out, int out_size)
{
    const float* x   = (const float*)d_in[0];
    const int*   ei  = (const int*)  d_in[1];
    const float* Wl0 = (const float*)d_in[2];
    const float* bl0 = (const float*)d_in[3];
    const float* Wr0 = (const float*)d_in[4];
    const float* Wl1 = (const float*)d_in[5];
    const float* bl1 = (const float*)d_in[6];
    const float* Wr1 = (const float*)d_in[7];
    const float* Wl2 = (const float*)d_in[8];
    const float* bl2 = (const float*)d_in[9];
    const float* Wr2 = (const float*)d_in[10];
    float* out = (float*)d_out;

    float *P, *R, *H1, *H2;
    cudaGetSymbolAddress((void**)&P,  g_P);
    cudaGetSymbolAddress((void**)&R,  g_R);
    cudaGetSymbolAddress((void**)&H1, g_H1);
    cudaGetSymbolAddress((void**)&H2, g_H2);

    const int SMEM_G128 = (128 * 132 + 128 * 264) * (int)sizeof(float); // 202752
    const int SMEM_G48  = (128 * 132 + 128 * 104) * (int)sizeof(float); // 120832
    cudaFuncSetAttribute(k_gemm2<128>, cudaFuncAttributeMaxDynamicSharedMemorySize, SMEM_G128);
    cudaFuncSetAttribute(k_gemm2<48>,  cudaFuncAttributeMaxDynamicSharedMemorySize, SMEM_G48);

    // ---- CSR build ----
    k_zero_detect<<<(N_NODES + 255) / 256, 256>>>(ei);
    k_hist<<<(N_EDGES + 255) / 256, 256>>>(ei);
    int nsb = (N_NODES + 1023) / 1024;
    k_scan_blocks<<<nsb, 1024>>>();
    k_scan_sums<<<1, 32>>>(nsb);
    k_finalize<<<(N_NODES + 255) / 256, 256>>>();
    k_fillcsr<<<(N_EDGES + 255) / 256, 256>>>(ei);

    int gmb = (N_NODES + 127) / 128;   // 391
    int agb = (N_NODES * 32 + 255) / 256;

    // layer 0 (project-first; mean is linear)
    k_gemm2<128><<<gmb, 512, SMEM_G128>>>(x,  Wl0, Wr0, P, R, N_NODES, DF);
    k_aggr<<<agb, 256>>>(P, R, bl0, H1);
    // layer 1
    k_gemm2<128><<<gmb, 512, SMEM_G128>>>(H1, Wl1, Wr1, P, R, N_NODES, DF);
    k_aggr<<<agb, 256>>>(P, R, bl1, H2);
    // layer 2 (47-wide padded to 48) + fused normalize/log_softmax
    k_gemm2<48><<<gmb, 512, SMEM_G48>>>(H2, Wl2, Wr2, P, R, N_NODES, NC);
    k_aggr_out<<<agb, 256>>>(P, R, bl2, out);
}

// round 5
// speedup vs baseline: 2.6316x; 1.3731x over previous
#include <cuda_runtime.h>
#include <cuda_bf16.h>
#include <math.h>
#include <stdint.h>

#define N_NODES 50000
#define N_EDGES 600000
#define DF      128
#define NC      47
#define LDC2    48

// ---------------- scratch ----------------------------------------------------
__device__ int   g_is64;
__device__ int   g_cnt[N_NODES];
__device__ int   g_rowptr[N_NODES + 1];
__device__ int   g_fill[N_NODES];
__device__ int   g_col[N_EDGES];
__device__ float g_deginv[N_NODES];
__device__ volatile int g_agg[64];
__device__ volatile int g_flag[64];
__device__ __nv_bfloat16 g_P [N_NODES * DF];
__device__ __nv_bfloat16 g_R [N_NODES * DF];
__device__ __nv_bfloat16 g_H1[N_NODES * DF];
__device__ __nv_bfloat16 g_H2[N_NODES * DF];
// pre-packed bf16 k-major weight images, row stride 136:
// L0 @0 (256*136), L1 @34816, L2 @69632 (96*136)
__device__ __nv_bfloat16 g_Bt[82688];

// ---------------- bf16 helpers ------------------------------------------------
__device__ __forceinline__ float4 ld_bf4(const __nv_bfloat16* p) {
    uint2 u = *(const uint2*)p;
    __nv_bfloat162 a = *(__nv_bfloat162*)&u.x;
    __nv_bfloat162 b = *(__nv_bfloat162*)&u.y;
    float2 fa = __bfloat1622float2(a), fb = __bfloat1622float2(b);
    return make_float4(fa.x, fa.y, fb.x, fb.y);
}
__device__ __forceinline__ void st_bf4(__nv_bfloat16* p, float4 v) {
    __nv_bfloat162 a = __floats2bfloat162_rn(v.x, v.y);
    __nv_bfloat162 b = __floats2bfloat162_rn(v.z, v.w);
    uint2 u;
    u.x = *(uint32_t*)&a; u.y = *(uint32_t*)&b;
    *(uint2*)p = u;
}
__device__ __forceinline__ uint32_t pack_bf2(float x, float y) {
    __nv_bfloat162 a = __floats2bfloat162_rn(x, y);
    return *(uint32_t*)&a;
}

// ---------------- CSR build ---------------------------------------------------
__global__ void k_zero_detect(const int* __restrict__ w) {
    int i = blockIdx.x * blockDim.x + threadIdx.x;
    if (i < N_NODES) g_cnt[i] = 0;
    if (i < 64) { g_flag[i] = 0; g_agg[i] = 0; }
    if (blockIdx.x == 0 && threadIdx.x < 32) {
        int bad = 0;
        for (int j = threadIdx.x; j < 4096; j += 32)
            bad |= (w[2 * j + 1] != 0);
        unsigned m = __ballot_sync(0xffffffffu, bad);
        if (threadIdx.x == 0) g_is64 = (m == 0) ? 1 : 0;
    }
}

__device__ __forceinline__ int edge_src(const int* w, int e) {
    return g_is64 ? w[2 * e] : w[e];
}
__device__ __forceinline__ int edge_dst(const int* w, int e) {
    return g_is64 ? w[2 * (N_EDGES + e)] : w[N_EDGES + e];
}

__global__ void k_hist(const int* __restrict__ w) {
    int e = blockIdx.x * blockDim.x + threadIdx.x;
    if (e < N_EDGES) atomicAdd(&g_cnt[edge_dst(w, e)], 1);
}

// single-pass scan with cross-block lookback (49 blocks, all resident)
__global__ void k_scan_lb() {
    __shared__ int wsum[32];
    __shared__ int s_ex;
    int b = blockIdx.x;
    int i = b * 1024 + threadIdx.x;
    int lane = threadIdx.x & 31, warp = threadIdx.x >> 5;
    int v = (i < N_NODES) ? g_cnt[i] : 0;
    int s = v;
    #pragma unroll
    for (int off = 1; off < 32; off <<= 1) {
        int t = __shfl_up_sync(0xffffffffu, s, off);
        if (lane >= off) s += t;
    }
    if (lane == 31) wsum[warp] = s;
    __syncthreads();
    if (warp == 0) {
        int ws = wsum[lane];
        #pragma unroll
        for (int off = 1; off < 32; off <<= 1) {
            int t = __shfl_up_sync(0xffffffffu, ws, off);
            if (lane >= off) ws += t;
        }
        wsum[lane] = ws;
    }
    __syncthreads();
    int incl = s + (warp ? wsum[warp - 1] : 0);
    if (threadIdx.x == 1023) {
        g_agg[b] = incl;
        __threadfence();
        g_flag[b] = 1;
    }
    if (warp == 0) {
        int ex = 0;
        for (int j = lane; j < b; j += 32) {
            while (g_flag[j] == 0) { }
            ex += g_agg[j];
        }
        #pragma unroll
        for (int o = 16; o; o >>= 1) ex += __shfl_xor_sync(0xffffffffu, ex, o);
        if (lane == 0) s_ex = ex;
    }
    __syncthreads();
    int r = s_ex + incl - v;
    if (i < N_NODES) {
        g_rowptr[i] = r;
        g_fill[i]   = r;
        g_deginv[i] = 1.0f / (float)(v > 1 ? v : 1);
    }
    if (i == 0) g_rowptr[N_NODES] = N_EDGES;
}

__global__ void k_fillcsr(const int* __restrict__ w) {
    int e = blockIdx.x * blockDim.x + threadIdx.x;
    if (e < N_EDGES) {
        int d = edge_dst(w, e);
        int s = edge_src(w, e);
        int pos = atomicAdd(&g_fill[d], 1);
        g_col[pos] = s;
    }
}

// ------- weight prep: k-major bf16 images, row stride 136 --------------------
// Image per layer: [2*NPER n-rows][136 k], element (n,k) = W(k,col(n)) bf16.
__global__ void k_prepB(const float* __restrict__ Wl0, const float* __restrict__ Wr0,
                        const float* __restrict__ Wl1, const float* __restrict__ Wr1,
                        const float* __restrict__ Wl2, const float* __restrict__ Wr2)
{
    int i = blockIdx.x * blockDim.x + threadIdx.x;   // 77824 real elements
    if (i >= 77824) return;
    const float *Wl, *Wr;
    __nv_bfloat16* out;
    int NPER, F, li;
    if (i < 32768)      { li = i;         Wl = Wl0; Wr = Wr0; out = g_Bt;         NPER = 128; F = 128; }
    else if (i < 65536) { li = i - 32768; Wl = Wl1; Wr = Wr1; out = g_Bt + 34816; NPER = 128; F = 128; }
    else                { li = i - 65536; Wl = Wl2; Wr = Wr2; out = g_Bt + 69632; NPER = 48;  F = 47;  }
    int n = li >> 7, k = li & 127;
    int col = (n < NPER) ? n : n - NPER;
    const float* W = (n < NPER) ? Wl : Wr;
    float v = (col < F) ? W[(size_t)k * F + col] : 0.f;
    out[(size_t)n * 136 + k] = __float2bfloat16_rn(v);
}

// ---------------- fused dual bf16 tensor-core GEMM ---------------------------
// P = A@Wl, R = A@Wr (bf16 in, fp32 acc, bf16 out). Block = 128 rows,
// 512 threads, 16 warps (4m x 4n), warp tile 32 x NW, mma.m16n8k16.
__device__ __forceinline__ void mma_bf16(float* d, const uint32_t* a, const uint32_t* b) {
    asm volatile(
        "mma.sync.aligned.m16n8k16.row.col.f32.bf16.bf16.f32 "
        "{%0,%1,%2,%3},{%4,%5,%6,%7},{%8,%9},{%0,%1,%2,%3};"
        : "+f"(d[0]), "+f"(d[1]), "+f"(d[2]), "+f"(d[3])
        : "r"(a[0]), "r"(a[1]), "r"(a[2]), "r"(a[3]), "r"(b[0]), "r"(b[1]));
}

template<int NPER, bool INF32>   // NPER: 128 hidden / 48 classifier
__global__ void __launch_bounds__(512, 1)
k_gemm2(const void* __restrict__ Ain, const __nv_bfloat16* __restrict__ Bimg,
        __nv_bfloat16* __restrict__ P, __nv_bfloat16* __restrict__ R, int M, int F)
{
    constexpr int BN  = 2 * NPER;          // 256 or 96
    constexpr int NW  = BN / 4;            // 64 or 24
    constexpr int NJ  = NW / 8;            // 8 or 3
    constexpr int AST = 136;               // bf16 stride; bank-conflict-free
    constexpr int BST = 136;
    extern __shared__ __nv_bfloat16 smh[];
    __nv_bfloat16* As = smh;               // [128][AST] row-major (m,k)
    __nv_bfloat16* Bs = smh + 128 * AST;   // [BN][BST]  k-major   (n,k)

    int bm = blockIdx.x * 128;
    int t  = threadIdx.x;

    // ---- A tile -> smem bf16
    if constexpr (INF32) {
        const float* A = (const float*)Ain;
        #pragma unroll
        for (int it = 0; it < 8; it++) {
            int lin = t + it * 512;            // 4096 x float4
            int row = lin >> 5, c4 = (lin & 31) << 2;
            float4 v = make_float4(0.f, 0.f, 0.f, 0.f);
            if (bm + row < M) v = *(const float4*)(A + (size_t)(bm + row) * DF + c4);
            uint2 u;
            u.x = pack_bf2(v.x, v.y);
            u.y = pack_bf2(v.z, v.w);
            *(uint2*)(As + row * AST + c4) = u;
        }
    } else {
        const __nv_bfloat16* A = (const __nv_bfloat16*)Ain;
        #pragma unroll
        for (int it = 0; it < 4; it++) {
            int lin = t + it * 512;            // 2048 x (8 bf16)
            int row = lin >> 4, c8 = (lin & 15) << 3;
            uint4 u = make_uint4(0u, 0u, 0u, 0u);
            if (bm + row < M) u = *(const uint4*)(A + (size_t)(bm + row) * DF + c8);
            *(uint4*)(As + row * AST + c8) = u;
        }
    }
    // ---- B image: straight vector copy (pre-packed, padded)
    {
        constexpr int CH = BN * BST * 2 / 16;   // 16B chunks
        const uint4* src = (const uint4*)Bimg;
        uint4* dst = (uint4*)Bs;
        #pragma unroll 4
        for (int i = t; i < CH; i += 512) dst[i] = src[i];
    }
    __syncthreads();

    int warp = t >> 5, lane = t & 31;
    int wm = (warp & 3) * 32;
    int wn = (warp >> 2) * NW;
    int group = lane >> 2, tig = lane & 3;

    float acc[2][NJ][4];
    #pragma unroll
    for (int i = 0; i < 2; i++)
        #pragma unroll
        for (int j = 0; j < NJ; j++)
            #pragma unroll
            for (int q = 0; q < 4; q++) acc[i][j][q] = 0.f;

    #pragma unroll
    for (int k0 = 0; k0 < DF; k0 += 16) {
        uint32_t a[2][4], b[NJ][2];
        #pragma unroll
        for (int i = 0; i < 2; i++) {
            const __nv_bfloat16* p = As + (wm + i * 16 + group) * AST + k0 + tig * 2;
            a[i][0] = *(const uint32_t*)p;
            a[i][1] = *(const uint32_t*)(p + 8 * AST);
            a[i][2] = *(const uint32_t*)(p + 8);
            a[i][3] = *(const uint32_t*)(p + 8 * AST + 8);
        }
        #pragma unroll
        for (int j = 0; j < NJ; j++) {
            const __nv_bfloat16* p = Bs + (size_t)(wn + j * 8 + group) * BST + k0 + tig * 2;
            b[j][0] = *(const uint32_t*)p;
            b[j][1] = *(const uint32_t*)(p + 8);
        }
        #pragma unroll
        for (int i = 0; i < 2; i++)
            #pragma unroll
            for (int j = 0; j < NJ; j++)
                mma_bf16(acc[i][j], a[i], b[j]);
    }

    // ---- epilogue: bf16x2 stores; n < NPER -> P else R; zero-pad cols >= F
    #pragma unroll
    for (int i = 0; i < 2; i++) {
        int gm0 = bm + wm + i * 16 + group;
        #pragma unroll
        for (int j = 0; j < NJ; j++) {
            int gn = wn + j * 8 + 2 * tig;
            __nv_bfloat16* dst;
            int col;
            if (gn < NPER) { dst = P; col = gn; }
            else           { dst = R; col = gn - NPER; }
            float v0 = (col     < F) ? acc[i][j][0] : 0.f;
            float v1 = (col + 1 < F) ? acc[i][j][1] : 0.f;
            float v2 = (col     < F) ? acc[i][j][2] : 0.f;
            float v3 = (col + 1 < F) ? acc[i][j][3] : 0.f;
            if (gm0 < M)
                *(uint32_t*)(dst + (size_t)gm0 * NPER + col) = pack_bf2(v0, v1);
            if (gm0 + 8 < M)
                *(uint32_t*)(dst + (size_t)(gm0 + 8) * NPER + col) = pack_bf2(v2, v3);
        }
    }
}

// -------- aggregation (hidden): OUT = relu(mean_nbr(P)+b+R), bf16 I/O -------
__global__ void k_aggr(const __nv_bfloat16* __restrict__ P,
                       const __nv_bfloat16* __restrict__ R,
                       const float* __restrict__ bias,
                       __nv_bfloat16* __restrict__ OUT)
{
    int gw   = (blockIdx.x * blockDim.x + threadIdx.x) >> 5;
    int lane = threadIdx.x & 31;
    if (gw >= N_NODES) return;
    int start = g_rowptr[gw], end = g_rowptr[gw + 1];

    int c0 = lane << 2;
    float4 acc = make_float4(0.f, 0.f, 0.f, 0.f);
    const __nv_bfloat16* base = P + c0;
    for (int e = start; e < end; e++) {
        int c = g_col[e];
        float4 p = ld_bf4(base + (size_t)c * DF);
        acc.x += p.x; acc.y += p.y; acc.z += p.z; acc.w += p.w;
    }
    float inv = g_deginv[gw];
    float4 r = ld_bf4(R + (size_t)gw * DF + c0);
    float4 b = *(const float4*)(bias + c0);
    float4 ov;
    ov.x = fmaxf(acc.x * inv + b.x + r.x, 0.f);
    ov.y = fmaxf(acc.y * inv + b.y + r.y, 0.f);
    ov.z = fmaxf(acc.z * inv + b.z + r.z, 0.f);
    ov.w = fmaxf(acc.w * inv + b.w + r.w, 0.f);
    st_bf4(OUT + (size_t)gw * DF + c0, ov);
}

// -------- fused layer-2: aggr + L2-normalize + log_softmax -> fp32 out ------
__global__ void k_aggr_out(const __nv_bfloat16* __restrict__ P,
                           const __nv_bfloat16* __restrict__ R,
                           const float* __restrict__ bias,
                           float* __restrict__ out)
{
    int gw   = (blockIdx.x * blockDim.x + threadIdx.x) >> 5;
    int lane = threadIdx.x & 31;
    if (gw >= N_NODES) return;
    bool act = (lane < 12);                    // 12 lanes x 4 = 48 cols
    int c0 = lane << 2;

    float v[4] = {0.f, 0.f, 0.f, 0.f};
    if (act) {
        int start = g_rowptr[gw], end = g_rowptr[gw + 1];
        float4 acc = make_float4(0.f, 0.f, 0.f, 0.f);
        const __nv_bfloat16* base = P + c0;
        for (int e = start; e < end; e++) {
            int c = g_col[e];
            float4 p = ld_bf4(base + (size_t)c * LDC2);
            acc.x += p.x; acc.y += p.y; acc.z += p.z; acc.w += p.w;
        }
        float inv = g_deginv[gw];
        float4 r = ld_bf4(R + (size_t)gw * LDC2 + c0);
        float av[4] = {acc.x, acc.y, acc.z, acc.w};
        float rv[4] = {r.x, r.y, r.z, r.w};
        #pragma unroll
        for (int j = 0; j < 4; j++) {
            int cc = c0 + j;
            if (cc < NC) v[j] = av[j] * inv + bias[cc] + rv[j];
        }
    }

    float ss = v[0]*v[0] + v[1]*v[1] + v[2]*v[2] + v[3]*v[3];
    #pragma unroll
    for (int o = 16; o; o >>= 1) ss += __shfl_xor_sync(0xffffffffu, ss, o);
    float inv = 1.0f / fmaxf(sqrtf(ss), 1e-12f);
    #pragma unroll
    for (int j = 0; j < 4; j++) v[j] *= inv;

    float m = -1e30f;
    #pragma unroll
    for (int j = 0; j < 4; j++)
        if (act && (c0 + j) < NC) m = fmaxf(m, v[j]);
    #pragma unroll
    for (int o = 16; o; o >>= 1) m = fmaxf(m, __shfl_xor_sync(0xffffffffu, m, o));

    float s = 0.f;
    #pragma unroll
    for (int j = 0; j < 4; j++)
        if (act && (c0 + j) < NC) s += expf(v[j] - m);
    #pragma unroll
    for (int o = 16; o; o >>= 1) s += __shfl_xor_sync(0xffffffffu, s, o);
    float ls = m + logf(s);

    if (act) {
        #pragma unroll
        for (int j = 0; j < 4; j++) {
            int cc = c0 + j;
            if (cc < NC) out[(size_t)gw * NC + cc] = v[j] - ls;
        }
    }
}

// ---------------- host --------------------------------------------------------
extern "C" void kernel_launch(void* const* d_in, const int* in_sizes, int n_in,
                              void* d_out, int out_size)
{
    const float* x   = (const float*)d_in[0];
    const int*   ei  = (const int*)  d_in[1];
    const float* Wl0 = (const float*)d_in[2];
    const float* bl0 = (const float*)d_in[3];
    const float* Wr0 = (const float*)d_in[4];
    const float* Wl1 = (const float*)d_in[5];
    const float* bl1 = (const float*)d_in[6];
    const float* Wr1 = (const float*)d_in[7];
    const float* Wl2 = (const float*)d_in[8];
    const float* bl2 = (const float*)d_in[9];
    const float* Wr2 = (const float*)d_in[10];
    float* out = (float*)d_out;

    __nv_bfloat16 *P, *R, *H1, *H2, *Bt;
    cudaGetSymbolAddress((void**)&P,  g_P);
    cudaGetSymbolAddress((void**)&R,  g_R);
    cudaGetSymbolAddress((void**)&H1, g_H1);
    cudaGetSymbolAddress((void**)&H2, g_H2);
    cudaGetSymbolAddress((void**)&Bt, g_Bt);

    const int SMEM_128 = (128 * 136 + 256 * 136) * 2;   // 104448
    const int SMEM_48  = (128 * 136 +  96 * 136) * 2;   //  60928
    cudaFuncSetAttribute(k_gemm2<128, true>,  cudaFuncAttributeMaxDynamicSharedMemorySize, SMEM_128);
    cudaFuncSetAttribute(k_gemm2<128, false>, cudaFuncAttributeMaxDynamicSharedMemorySize, SMEM_128);
    cudaFuncSetAttribute(k_gemm2<48,  false>, cudaFuncAttributeMaxDynamicSharedMemorySize, SMEM_48);

    // CSR build
    k_zero_detect<<<(N_NODES + 255) / 256, 256>>>(ei);
    k_hist<<<(N_EDGES + 255) / 256, 256>>>(ei);
    k_scan_lb<<<(N_NODES + 1023) / 1024, 1024>>>();
    k_fillcsr<<<(N_EDGES + 255) / 256, 256>>>(ei);

    // weight images (bf16, k-major, padded stride)
    k_prepB<<<(77824 + 255) / 256, 256>>>(Wl0, Wr0, Wl1, Wr1, Wl2, Wr2);

    int gmb = (N_NODES + 127) / 128;   // 391
    int agb = (N_NODES * 32 + 255) / 256;

    // layer 0 (project-first; mean is linear); x is fp32
    k_gemm2<128, true ><<<gmb, 512, SMEM_128>>>(x,  Bt,         P, R, N_NODES, DF);
    k_aggr<<<agb, 256>>>(P, R, bl0, H1);
    // layer 1 (bf16 activations)
    k_gemm2<128, false><<<gmb, 512, SMEM_128>>>(H1, Bt + 34816, P, R, N_NODES, DF);
    k_aggr<<<agb, 256>>>(P, R, bl1, H2);
    // layer 2 (47 padded to 48) + fused normalize/log_softmax
    k_gemm2<48,  false><<<gmb, 512, SMEM_48>>>(H2, Bt + 69632, P, R, N_NODES, NC);
    k_aggr_out<<<agb, 256>>>(P, R, bl2, out);
}